// round 3
// baseline (speedup 1.0000x reference)
#include <cuda_runtime.h>

// Fixed shapes
#define NB      64
#define T_LEN   2048
#define DDIM    80
#define N_ROWS  (NB * T_LEN)          // 131072
#define N_ELEM  (N_ROWS * DDIM)       // 10,485,760
#define VPR     (DDIM / 4)            // 20 float4 per row

#define GTHREADS 128
#define GBLOCKS  (N_ROWS / GTHREADS)  // 1024 blocks, one row per thread

// Scratch (no allocation allowed)
__device__ float        g_pc[GBLOCKS];
__device__ float        g_pl[GBLOCKS];
__device__ unsigned int g_count = 0;
__device__ __align__(16) float g_zero[DDIM];   // zero-initialized row

__device__ __forceinline__ float ex2f(float x) {
    float y; asm("ex2.approx.f32 %0, %1;" : "=f"(y) : "f"(x)); return y;
}
__device__ __forceinline__ float lg2f(float x) {
    float y; asm("lg2.approx.f32 %0, %1;" : "=f"(y) : "f"(x)); return y;
}

// One element: 9 shifted abs-diffs -> sum of exp2(C*|d|); center diff tracked.
__device__ __forceinline__ void elem(float xv,
                                     float u0, float u1, float u2,
                                     float m0, float m1, float m2,
                                     float b0, float b1, float b2,
                                     float& accC, float& accL)
{
    const float C = -46.166241308446828f;   // -32 * log2(e)
    float dc = xv - m1;                     // center (unshifted) diff
    float e0 = ex2f(C * fabsf(xv - u0));
    float e1 = ex2f(C * fabsf(xv - u1));
    float e2 = ex2f(C * fabsf(xv - u2));
    float e3 = ex2f(C * fabsf(xv - m0));
    float e4 = ex2f(C * fabsf(dc));
    float e5 = ex2f(C * fabsf(xv - m2));
    float e6 = ex2f(C * fabsf(xv - b0));
    float e7 = ex2f(C * fabsf(xv - b1));
    float e8 = ex2f(C * fabsf(xv - b2));
    float s = (((e0 + e1) + (e2 + e3)) + ((e4 + e5) + (e6 + e7))) + e8;
    accC += fabsf(dc);
    accL += lg2f(fmaxf(s, 1e-37f));
}

__global__ void __launch_bounds__(GTHREADS)
jitter_fused(const float* __restrict__ in, const float* __restrict__ tg,
             float* __restrict__ out)
{
    const unsigned row = blockIdx.x * GTHREADS + threadIdx.x;  // < N_ROWS
    const unsigned i   = row & (T_LEN - 1);

    const float* rowI = in + (size_t)row * DDIM;
    const float* rowM = tg + (size_t)row * DDIM;
    const float* rowU = (i > 0)         ? rowM - DDIM : g_zero;
    const float* rowD = (i < T_LEN - 1) ? rowM + DDIM : g_zero;

    float accC = 0.0f;
    float accL = 0.0f;

    // sliding window state: left scalar + current float4 per target row
    float  lu = 0.0f, lm = 0.0f, lb = 0.0f;
    float4 cu = *reinterpret_cast<const float4*>(rowU);
    float4 cm = *reinterpret_cast<const float4*>(rowM);
    float4 cb = *reinterpret_cast<const float4*>(rowD);

    #pragma unroll 5
    for (int j = 0; j < VPR; j++) {
        float4 nu = {0.f, 0.f, 0.f, 0.f};
        float4 nm = {0.f, 0.f, 0.f, 0.f};
        float4 nb = {0.f, 0.f, 0.f, 0.f};
        if (j < VPR - 1) {
            nu = *reinterpret_cast<const float4*>(rowU + 4 * j + 4);
            nm = *reinterpret_cast<const float4*>(rowM + 4 * j + 4);
            nb = *reinterpret_cast<const float4*>(rowD + 4 * j + 4);
        }
        float4 x = *reinterpret_cast<const float4*>(rowI + 4 * j);

        elem(x.x, lu,   cu.x, cu.y,  lm,   cm.x, cm.y,  lb,   cb.x, cb.y, accC, accL);
        elem(x.y, cu.x, cu.y, cu.z,  cm.x, cm.y, cm.z,  cb.x, cb.y, cb.z, accC, accL);
        elem(x.z, cu.y, cu.z, cu.w,  cm.y, cm.z, cm.w,  cb.y, cb.z, cb.w, accC, accL);
        elem(x.w, cu.z, cu.w, nu.x,  cm.z, cm.w, nm.x,  cb.z, cb.w, nb.x, accC, accL);

        lu = cu.w; lm = cm.w; lb = cb.w;
        cu = nu;   cm = nm;   cb = nb;
    }

    // deterministic block tree reduction
    __shared__ float shc[GTHREADS];
    __shared__ float shl[GTHREADS];
    shc[threadIdx.x] = accC;
    shl[threadIdx.x] = accL;
    __syncthreads();
    #pragma unroll
    for (int off = GTHREADS / 2; off > 0; off >>= 1) {
        if (threadIdx.x < off) {
            shc[threadIdx.x] += shc[threadIdx.x + off];
            shl[threadIdx.x] += shl[threadIdx.x + off];
        }
        __syncthreads();
    }

    __shared__ bool isLast;
    if (threadIdx.x == 0) {
        g_pc[blockIdx.x] = shc[0];
        g_pl[blockIdx.x] = shl[0];
        __threadfence();
        unsigned ticket = atomicAdd(&g_count, 1u);
        isLast = (ticket == GBLOCKS - 1);
    }
    __syncthreads();

    if (isLast) {
        __shared__ double dc_sh[GTHREADS];
        __shared__ double dl_sh[GTHREADS];
        double dc = 0.0, dl = 0.0;
        for (int k = threadIdx.x; k < GBLOCKS; k += GTHREADS) {
            dc += (double)__ldcg(&g_pc[k]);
            dl += (double)__ldcg(&g_pl[k]);
        }
        dc_sh[threadIdx.x] = dc;
        dl_sh[threadIdx.x] = dl;
        __syncthreads();
        #pragma unroll
        for (int off = GTHREADS / 2; off > 0; off >>= 1) {
            if (threadIdx.x < off) {
                dc_sh[threadIdx.x] += dc_sh[threadIdx.x + off];
                dl_sh[threadIdx.x] += dl_sh[threadIdx.x + off];
            }
            __syncthreads();
        }
        if (threadIdx.x == 0) {
            const double C2d = -0.021660849392498291;  // -ln(2)/32
            double res = (0.5 / (double)N_ELEM) * (dc_sh[0] + C2d * dl_sh[0]);
            out[0] = (float)res;
            g_count = 0;   // reset ticket for graph replay
        }
    }
}

extern "C" void kernel_launch(void* const* d_in, const int* in_sizes, int n_in,
                              void* d_out, int out_size)
{
    const float* in = (const float*)d_in[0];
    const float* tg = (const float*)d_in[1];
    float* out = (float*)d_out;

    jitter_fused<<<GBLOCKS, GTHREADS>>>(in, tg, out);
}